// round 12
// baseline (speedup 1.0000x reference)
#include <cuda_runtime.h>
#include <cuda_fp16.h>
#include <cuda_bf16.h>

#define DD 96
#define HH 128
#define WW 160
#define NPTS (DD*HH*WW)          // 1,966,080
#define PBLK 256                 // prep block
#define PGRID 1216               // prep persistent grid (152 SMs * 8)
#define BLK 128                  // warp kernel block
#define PPT 4                    // points per thread (strided by BLK)
#define PPB (BLK*PPT)            // 512 points per block
// warp grid = NPTS/PPB = 3840 blocks

// fp16 2x2 (y,x) corner-patch table, one entry per (z,y,x):
//   .x = half2(v[z,y ,x ])   .y = half2(v[z,y ,x1])
//   .z = half2(v[z,y1,x ])   .w = half2(v[z,y1,x1])   (x1,y1 border-clamped)
__device__ uint4 g_patch[NPTS];

static __device__ __forceinline__ unsigned packh2(float2 v) {
    __half2 h = __float22half2_rn(v);
    return *reinterpret_cast<unsigned*>(&h);
}

// ---------------------------------------------------------------------------
// Prep: persistent grid-stride (measured ~5.7us, near BW floor)
__global__ __launch_bounds__(PBLK) void nse_prep_kernel(
    const float* __restrict__ src)
{
    const float2* __restrict__ v2 = (const float2*)src;
    for (int m = blockIdx.x * PBLK + threadIdx.x; m < NPTS; m += PGRID * PBLK) {
        unsigned r = (unsigned)m / 160u;
        unsigned x = (unsigned)m - r * 160u;
        unsigned y = r & 127u;

        const int mx  = (x < WW - 1) ? m + 1  : m;
        const int my  = (y < HH - 1) ? m + WW : m;
        const int mxy = (x < WW - 1) ? my + 1 : my;

        float2 a = __ldg(&v2[m]);
        float2 b = __ldg(&v2[mx]);
        float2 c = __ldg(&v2[my]);
        float2 d = __ldg(&v2[mxy]);

        uint4 o;
        o.x = packh2(a); o.y = packh2(b); o.z = packh2(c); o.w = packh2(d);
        g_patch[m] = o;
    }
}

// ---------------------------------------------------------------------------
// Warp: PPT=4, strided point assignment, 10 blocks/SM (regs<=51),
// 8 batched gathers per thread for maximum in-flight MLP.
__global__ __launch_bounds__(BLK, 10) void nse_warp_kernel(
    const float* __restrict__ flow,   // (N,7): t(3), qv(3), qw(1)
    float* __restrict__ out)          // [warped 2N | new_loc 3N | grid 3N]
{
    __shared__ float sflow[PPB * 7];  // 14336 B

    const int tid = threadIdx.x;
    const int n0  = blockIdx.x * PPB;

    // Coalesced stage of this block's 512 flow rows (streaming).
    const float* fsrc = flow + (size_t)n0 * 7;
    #pragma unroll
    for (int i = 0; i < 7 * PPT; ++i)
        sflow[tid + i * BLK] = __ldcs(&fsrc[tid + i * BLK]);
    __syncthreads();

    float wxv[PPT], wyv[PPT], wzv[PPT];
    int   m0[PPT], m1[PPT];

    // Per-point math; store gather-independent outputs immediately so their
    // registers die before the gather block.
    #pragma unroll
    for (int p = 0; p < PPT; ++p) {
        const int n = n0 + p * BLK + tid;     // strided assignment

        unsigned r = (unsigned)n / 160u;
        unsigned k = (unsigned)n - r * 160u;
        unsigned j = r & 127u;
        unsigned i = r >> 7;

        const float inv_mx = 1.0f / 159.0f;
        float gx = (2.0f * (float)i -  95.0f) * inv_mx;
        float gy = (2.0f * (float)j - 127.0f) * inv_mx;
        float gz = (2.0f * (float)k - 159.0f) * inv_mx;

        // bank = 7*tid mod 32, gcd(7,32)=1 -> conflict-free scalar LDS
        const float* f = &sflow[(p * BLK + tid) * 7];
        float tx = f[0], ty = f[1], tz = f[2];
        float qx = f[3], qy = f[4], qz = f[5], qw = f[6];

        float uvx = qy * gz - qz * gy + qw * gx;
        float uvy = qz * gx - qx * gz + qw * gy;
        float uvz = qx * gy - qy * gx + qw * gz;
        float Rx = gx + 2.0f * (qy * uvz - qz * uvy) + tx;
        float Ry = gy + 2.0f * (qz * uvx - qx * uvz) + ty;
        float Rz = gz + 2.0f * (qx * uvy - qy * uvx) + tz;

        // Coalesced scalar streaming stores (lane-consecutive addresses).
        __stcs(&out[2 * NPTS + n], Rx);
        __stcs(&out[3 * NPTS + n], Ry);
        __stcs(&out[4 * NPTS + n], Rz);
        __stcs(&out[5 * NPTS + n], gx);
        __stcs(&out[6 * NPTS + n], gy);
        __stcs(&out[7 * NPTS + n], gz);

        float ix = fminf(fmaxf(0.5f * (Rz * 159.0f + 159.0f), 0.0f), 159.0f);
        float iy = fminf(fmaxf(0.5f * (Ry * 159.0f + 127.0f), 0.0f), 127.0f);
        float iz = fminf(fmaxf(0.5f * (Rx * 159.0f +  95.0f), 0.0f),  95.0f);

        int x0 = (int)ix, y0 = (int)iy, z0 = (int)iz;
        int z1 = min(z0 + 1, DD - 1);

        wxv[p] = ix - (float)x0;
        wyv[p] = iy - (float)y0;
        wzv[p] = iz - (float)z0;

        int base = y0 * WW + x0;
        m0[p] = z0 * (HH * WW) + base;
        m1[p] = z1 * (HH * WW) + base;
    }

    // Batch all 8 gathers for maximum in-flight MLP.
    uint4 P0[PPT], P1[PPT];
    #pragma unroll
    for (int p = 0; p < PPT; ++p) {
        P0[p] = __ldg(&g_patch[m0[p]]);
        P1[p] = __ldg(&g_patch[m1[p]]);
    }

    #pragma unroll
    for (int p = 0; p < PPT; ++p) {
        const int n = n0 + p * BLK + tid;
        float wx = wxv[p], wy = wyv[p], wz = wzv[p];
        float ux = 1.0f - wx, uy = 1.0f - wy, uz = 1.0f - wz;

        float2 a0 = __half22float2(*reinterpret_cast<const __half2*>(&P0[p].x));
        float2 b0 = __half22float2(*reinterpret_cast<const __half2*>(&P0[p].y));
        float2 c0 = __half22float2(*reinterpret_cast<const __half2*>(&P0[p].z));
        float2 d0 = __half22float2(*reinterpret_cast<const __half2*>(&P0[p].w));
        float s0x = (a0.x * ux + b0.x * wx) * uy + (c0.x * ux + d0.x * wx) * wy;
        float s0y = (a0.y * ux + b0.y * wx) * uy + (c0.y * ux + d0.y * wx) * wy;

        float2 a1 = __half22float2(*reinterpret_cast<const __half2*>(&P1[p].x));
        float2 b1 = __half22float2(*reinterpret_cast<const __half2*>(&P1[p].y));
        float2 c1 = __half22float2(*reinterpret_cast<const __half2*>(&P1[p].z));
        float2 d1 = __half22float2(*reinterpret_cast<const __half2*>(&P1[p].w));
        float s1x = (a1.x * ux + b1.x * wx) * uy + (c1.x * ux + d1.x * wx) * wy;
        float s1y = (a1.y * ux + b1.y * wx) * uy + (c1.y * ux + d1.y * wx) * wy;

        __stcs(&out[n],        s0x * uz + s1x * wz);
        __stcs(&out[NPTS + n], s0y * uz + s1y * wz);
    }
}

extern "C" void kernel_launch(void* const* d_in, const int* in_sizes, int n_in,
                              void* d_out, int out_size) {
    const float* src  = (const float*)d_in[0];
    const float* flow = (const float*)d_in[1];
    if (n_in >= 2 && in_sizes[0] == 7 * NPTS && in_sizes[1] == 2 * NPTS) {
        src  = (const float*)d_in[1];
        flow = (const float*)d_in[0];
    }
    float* out = (float*)d_out;
    nse_prep_kernel<<<PGRID, PBLK>>>(src);
    nse_warp_kernel<<<NPTS / PPB, BLK>>>(flow, out);
}